// round 6
// baseline (speedup 1.0000x reference)
#include <cuda_runtime.h>
#include <cstdint>
#include <math.h>

#define HH 96
#define WW 96
#define HW 9216

typedef unsigned long long ull;

// device scratch (no allocations allowed)
__device__ float g_mask[4*9*HW];     // sigmoid(mask conv)
__device__ float g_wt[9*64*64];      // transposed weight [kt][c][o]

#define FMA2(a,b,c) asm("fma.rn.f32x2 %0, %1, %2, %0;" : "+l"(a) : "l"(b), "l"(c))

__device__ __forceinline__ ull dup2(float w) {
    unsigned int u = __float_as_uint(w);
    ull r;
    asm("mov.b64 %0, {%1, %1};" : "=l"(r) : "r"(u));
    return r;
}

// ---------------- kernel 1: mask conv + sigmoid + weight transpose ----------------
__global__ __launch_bounds__(256) void k_mask(const float* __restrict__ x,
                                              const float* __restrict__ mw,
                                              const float* __restrict__ mb,
                                              const float* __restrict__ wgt) {
    __shared__ float smw[64*84];
    __shared__ float sbias[9];
    int tid = threadIdx.x;

    // merged weight transpose: one element per thread (36864 = 9*64*64 exactly)
    {
        int e = blockIdx.x*256 + tid;
        int o = e & 63, c = (e >> 6) & 63, kt = e >> 12;
        g_wt[e] = wgt[o*576 + c*9 + kt];
    }

    for (int i = tid; i < 5184; i += 256) {
        int k = i / 576; int r = i % 576; int c = r / 9; int t = r % 9;
        smw[c*84 + k*9 + t] = mw[i];
    }
    if (tid < 9) sbias[tid] = mb[tid];
    __syncthreads();

    int t = blockIdx.x*256 + tid;
    int b = t / HW; int r = t % HW; int h = r / WW; int w = r % WW;

    float acc[9];
    #pragma unroll
    for (int k = 0; k < 9; k++) acc[k] = sbias[k];

    const float* xb = x + (size_t)b*64*HW;
    for (int c = 0; c < 64; c++) {
        float v[9];
        #pragma unroll
        for (int i = 0; i < 3; i++)
          #pragma unroll
          for (int j = 0; j < 3; j++) {
            int yy = h + i - 1, xx = w + j - 1;
            bool ok = (yy >= 0) && (yy < HH) && (xx >= 0) && (xx < WW);
            v[i*3+j] = ok ? __ldg(xb + c*HW + yy*WW + xx) : 0.f;
          }
        const float* wr = smw + c*84;
        #pragma unroll
        for (int k = 0; k < 9; k++)
          #pragma unroll
          for (int tt = 0; tt < 9; tt++)
            acc[k] = fmaf(v[tt], wr[k*9 + tt], acc[k]);
    }
    #pragma unroll
    for (int k = 0; k < 9; k++) {
        float m = 1.f/(1.f + __expf(-acc[k]));
        g_mask[((b*9 + k)*HH + h)*WW + w] = m;
    }
}

// ---------------- kernel 2: fused sample + modulate + register-tiled GEMM ----------------
// block: 128 threads, 64 pixels. Gather: each thread does one pixel x 32 channels.
// GEMM: thread tile 8 outputs x 4 pixels (f32x2 over adjacent-pixel pairs).
__global__ __launch_bounds__(128) void k_deform(const float* __restrict__ x,
                                                const float* __restrict__ offset,
                                                float* __restrict__ out) {
    __shared__ float ssam[64*68];    // samples [c][pix], 4-pad
    __shared__ float swt[64*72];     // weights [c][o], 8-pad

    int tid  = threadIdx.x;
    int pxl  = tid & 63;             // gather pixel within tile
    int half = tid >> 6;             // channel half (0/1)
    int b    = blockIdx.y;
    int pix0 = blockIdx.x * 64;
    int pix  = pix0 + pxl;
    int ph   = pix / WW, pw = pix % WW;

    int og = tid & 7;                // output group (8 outputs)
    int pg = (tid >> 3) & 15;        // pixel group (4 pixels)

    const float* xb = x + (size_t)b*64*HW + (size_t)(half*32)*HW;

    ull acc[8][2];
    #pragma unroll
    for (int o = 0; o < 8; o++) { acc[o][0] = 0ULL; acc[o][1] = 0ULL; }

    for (int kt = 0; kt < 9; kt++) {
        __syncthreads();   // previous GEMM done before overwriting tiles

        // ---- stage this tap's weights [c][o]: 1024 float4, 8 per thread ----
        {
            const float4* wsrc = (const float4*)(g_wt + kt*4096);
            #pragma unroll
            for (int i = 0; i < 8; i++) {
                int idx = i*128 + tid;
                int c = idx >> 4, o4 = idx & 15;
                *(float4*)(swt + c*72 + o4*4) = wsrc[idx];
            }
        }

        // ---- per-pixel bilinear setup (registers only) ----
        int ky = kt / 3, kx = kt % 3;
        float oy = offset[(size_t)(b*18 + 2*kt    )*HW + pix];
        float ox = offset[(size_t)(b*18 + 2*kt + 1)*HW + pix];
        float m  = g_mask[(size_t)(b*9 + kt)*HW + pix];
        float py  = (float)(ph - 1 + ky) + oy;
        float pxf = (float)(pw - 1 + kx) + ox;
        float y0f = floorf(py), x0f = floorf(pxf);
        int   y0  = (int)y0f,   x0  = (int)x0f;
        float wy = py - y0f, wx = pxf - x0f;
        float w11 = m*wy*wx;
        float w10 = m*wy - w11;
        float w01 = m*wx - w11;
        float w00 = m - m*wy - m*wx + w11;
        bool ya = (y0 >=  0) & (y0 < HH);
        bool yb = (y0 >= -1) & (y0 < HH-1);
        bool xa = (x0 >=  0) & (x0 < WW);
        bool xc = (x0 >= -1) & (x0 < WW-1);
        if (!(ya & xa)) w00 = 0.f;
        if (!(ya & xc)) w01 = 0.f;
        if (!(yb & xa)) w10 = 0.f;
        if (!(yb & xc)) w11 = 0.f;
        int yc0 = min(max(y0,     0), HH-1), yc1 = min(max(y0 + 1, 0), HH-1);
        int xc0 = min(max(x0,     0), WW-1), xc1 = min(max(x0 + 1, 0), WW-1);
        int i00 = yc0*WW + xc0, i01 = yc0*WW + xc1;
        int i10 = yc1*WW + xc0, i11 = yc1*WW + xc1;

        // ---- gather 32 channels for this pixel ----
        {
            const float* xp = xb;
            float* sp = ssam + (half*32)*68 + pxl;
            #pragma unroll 8
            for (int c = 0; c < 32; c++) {
                float v = __ldg(xp + i00)*w00 + __ldg(xp + i01)*w01
                        + __ldg(xp + i10)*w10 + __ldg(xp + i11)*w11;
                sp[0] = v;
                sp += 68;
                xp += HW;
            }
        }
        __syncthreads();

        // ---- GEMM accumulate over this tap's 64 channels ----
        #pragma unroll 2
        for (int c = 0; c < 64; c++) {
            const float* wp = swt + c*72 + og*8;
            float4 wa = *(const float4*)(wp);
            float4 wb = *(const float4*)(wp + 4);
            ull wd[8];
            wd[0] = dup2(wa.x); wd[1] = dup2(wa.y);
            wd[2] = dup2(wa.z); wd[3] = dup2(wa.w);
            wd[4] = dup2(wb.x); wd[5] = dup2(wb.y);
            wd[6] = dup2(wb.z); wd[7] = dup2(wb.w);
            ulonglong2 s = *(const ulonglong2*)(ssam + c*68 + pg*4);
            #pragma unroll
            for (int o = 0; o < 8; o++) {
                FMA2(acc[o][0], wd[o], s.x);
                FMA2(acc[o][1], wd[o], s.y);
            }
        }
    }

    // ---- epilogue: direct packed stores (f32x2 lanes = adjacent pixels) ----
    float* ob = out + (size_t)b*64*HW + pix0 + pg*4;
    #pragma unroll
    for (int i = 0; i < 8; i++) {
        float* op = ob + (size_t)(og*8 + i)*HW;
        *(ull*)(op)     = acc[i][0];
        *(ull*)(op + 2) = acc[i][1];
    }
}

// ---------------- launch ----------------
extern "C" void kernel_launch(void* const* d_in, const int* in_sizes, int n_in,
                              void* d_out, int out_size) {
    const float* x      = (const float*)d_in[0];
    const float* offset = (const float*)d_in[1];
    const float* weight = (const float*)d_in[2];
    const float* mw     = (const float*)d_in[3];
    const float* mb     = (const float*)d_in[4];
    float* out = (float*)d_out;
    (void)in_sizes; (void)n_in; (void)out_size;

    k_mask<<<144, 256>>>(x, mw, mb, weight);
    dim3 grid(HW/64, 4);                 // (144, 4) = 576 blocks
    k_deform<<<grid, 128>>>(x, offset, out);
}

// round 8
// speedup vs baseline: 1.6390x; 1.6390x over previous
#include <cuda_runtime.h>
#include <cstdint>
#include <math.h>

#define HH 96
#define WW 96
#define HW 9216
typedef unsigned long long ull;

// device scratch (no allocations allowed)
__device__ float g_mask[4*9*HW];                  // sigmoid(mask conv)
__device__ float g_wt[9*64*64];                   // transposed weight [kt][c][o]
__device__ __align__(128) float g_xt[4*HW*64];    // x in NHWC: [b][h][w][c]

#define FMA2(a,b,c) asm("fma.rn.f32x2 %0, %1, %2, %0;" : "+l"(a) : "l"(b), "l"(c))
__device__ __forceinline__ ull dup2(float w) {
    unsigned int u = __float_as_uint(w); ull r;
    asm("mov.b64 %0, {%1, %1};" : "=l"(r) : "r"(u)); return r;
}

// ---------------- kernel 0: NCHW -> NHWC transpose ----------------
__global__ __launch_bounds__(256) void k_nhwc(const float* __restrict__ x) {
    __shared__ float tile[64][65];
    int t = threadIdx.x;
    int b = blockIdx.y;
    int px0 = blockIdx.x*64;
    int px = t & 63, cg = t >> 6;
    const float* xb = x + (size_t)b*64*HW + px0 + px;
    #pragma unroll
    for (int i = 0; i < 16; i++) {
        int c = cg*16 + i;
        tile[px][c] = xb[(size_t)c*HW];
    }
    __syncthreads();
    float* ob = g_xt + (size_t)b*HW*64 + (size_t)px0*64;
    #pragma unroll
    for (int jj = 0; jj < 4; jj++) {
        int id = jj*256 + t;
        int p = id >> 4, c16 = id & 15;
        // scalar LDS reads (tile rows are 260 B stride -> not float4-aligned)
        float4 v = make_float4(tile[p][c16*4], tile[p][c16*4+1],
                               tile[p][c16*4+2], tile[p][c16*4+3]);
        *(float4*)(ob + p*64 + c16*4) = v;
    }
}

// ---------------- kernel 1: mask conv + sigmoid + weight transpose ----------------
__global__ __launch_bounds__(256) void k_mask(const float* __restrict__ x,
                                              const float* __restrict__ mw,
                                              const float* __restrict__ mb,
                                              const float* __restrict__ wgt) {
    __shared__ float smw[64*84];
    __shared__ float sbias[9];
    int tid = threadIdx.x;
    {
        int e = blockIdx.x*256 + tid;        // 36864 = 9*64*64 exactly
        int o = e & 63, c = (e >> 6) & 63, kt = e >> 12;
        g_wt[e] = wgt[o*576 + c*9 + kt];
    }
    for (int i = tid; i < 5184; i += 256) {
        int k = i / 576; int r = i % 576; int c = r / 9; int t = r % 9;
        smw[c*84 + k*9 + t] = mw[i];
    }
    if (tid < 9) sbias[tid] = mb[tid];
    __syncthreads();

    int t = blockIdx.x*256 + tid;
    int b = t / HW; int r = t % HW; int h = r / WW; int w = r % WW;
    float acc[9];
    #pragma unroll
    for (int k = 0; k < 9; k++) acc[k] = sbias[k];
    const float* xb = x + (size_t)b*64*HW;
    for (int c = 0; c < 64; c++) {
        float v[9];
        #pragma unroll
        for (int i = 0; i < 3; i++)
          #pragma unroll
          for (int j = 0; j < 3; j++) {
            int yy = h + i - 1, xx = w + j - 1;
            bool ok = (yy >= 0) && (yy < HH) && (xx >= 0) && (xx < WW);
            v[i*3+j] = ok ? __ldg(xb + c*HW + yy*WW + xx) : 0.f;
          }
        const float* wr = smw + c*84;
        #pragma unroll
        for (int k = 0; k < 9; k++)
          #pragma unroll
          for (int tt = 0; tt < 9; tt++)
            acc[k] = fmaf(v[tt], wr[k*9 + tt], acc[k]);
    }
    #pragma unroll
    for (int k = 0; k < 9; k++) {
        float m = 1.f/(1.f + __expf(-acc[k]));
        g_mask[((b*9 + k)*HH + h)*WW + w] = m;
    }
}

// ---------------- kernel 2: NHWC gather + double-buffered register GEMM ----------------
#define S_SS 132
#define S_WT 68
#define SS_FL (64*S_SS)     // 8448
#define WT_FL (64*S_WT)     // 4352

__global__ __launch_bounds__(128) void k_deform(const float* __restrict__ offset,
                                                float* __restrict__ out) {
    extern __shared__ float sm[];
    float* ssamA = sm;
    float* ssamB = sm + SS_FL;
    float* swtA  = sm + 2*SS_FL;
    float* swtB  = swtA + WT_FL;
    float* spar  = swtA + 2*WT_FL;       // [128 px][8]

    int tid  = threadIdx.x;
    int wid  = tid >> 5, lane = tid & 31;
    int qh   = lane & 15;
    int hi   = lane >> 4;                // 0 = left x-corner, 1 = right
    int b    = blockIdx.y;
    int pix0 = blockIdx.x * 128;
    int og   = tid & 7, pg = tid >> 3;
    int gpx  = wid*32 + lane;            // this thread's param pixel (local)
    int mypix = pix0 + gpx;
    int ph = mypix / WW, pw = mypix % WW;
    const float* xb = g_xt + (size_t)b*HW*64;
    float* mypar = spar + gpx*8;

    ull acc[8][4];
    #pragma unroll
    for (int o = 0; o < 8; o++)
        #pragma unroll
        for (int k = 0; k < 4; k++) acc[o][k] = 0ULL;

    // ---- param compute for tap kt (lane-per-pixel) ----
    auto params = [&](int kt) {
        float oy = offset[(size_t)(b*18 + 2*kt    )*HW + mypix];
        float ox = offset[(size_t)(b*18 + 2*kt + 1)*HW + mypix];
        float mk = g_mask[(size_t)(b*9 + kt)*HW + mypix];
        int ky = kt/3, kx = kt - ky*3;
        float py  = (float)(ph - 1 + ky) + oy;
        float pxf = (float)(pw - 1 + kx) + ox;
        float y0f = floorf(py), x0f = floorf(pxf);
        int y0 = (int)y0f, x0 = (int)x0f;
        float wy = py - y0f, wx = pxf - x0f;
        float w11 = mk*wy*wx;
        float w10 = mk*wy - w11;
        float w01 = mk*wx - w11;
        float w00 = mk - mk*wy - mk*wx + w11;
        if (!((y0 >=  0) & (y0 < HH)   & (x0 >=  0) & (x0 < WW)))   w00 = 0.f;
        if (!((y0 >=  0) & (y0 < HH)   & (x0 >= -1) & (x0 < WW-1))) w01 = 0.f;
        if (!((y0 >= -1) & (y0 < HH-1) & (x0 >=  0) & (x0 < WW)))   w10 = 0.f;
        if (!((y0 >= -1) & (y0 < HH-1) & (x0 >= -1) & (x0 < WW-1))) w11 = 0.f;
        int yc0 = min(max(y0,   0), HH-1), yc1 = min(max(y0+1, 0), HH-1);
        int xc0 = min(max(x0,   0), WW-1), xc1 = min(max(x0+1, 0), WW-1);
        ((float4*)mypar)[0] = make_float4(w00, w01, w10, w11);
        ((float4*)mypar)[1] = make_float4(
            __int_as_float((yc0*WW + xc0)*64), __int_as_float((yc0*WW + xc1)*64),
            __int_as_float((yc1*WW + xc0)*64), __int_as_float((yc1*WW + xc1)*64));
    };

    auto stage_w = [&](int kt, float* dst) {
        const float4* wsrc = (const float4*)(g_wt + kt*4096);
        #pragma unroll
        for (int i = 0; i < 8; i++) {
            int idx = i*128 + tid;
            int c = idx >> 4, o4 = idx & 15;
            *(float4*)(dst + c*S_WT + o4*4) = wsrc[idx];
        }
    };

    float4 T[4], B[4];
    auto ldg_round = [&](int g) {
        int px0r = wid*32 + g*4;
        #pragma unroll
        for (int r = 0; r < 4; r++) {
            float4 pa = ((const float4*)(spar + (px0r + r)*8))[1];
            int aT = __float_as_int(hi ? pa.y : pa.x) + qh*4;
            int aB = __float_as_int(hi ? pa.w : pa.z) + qh*4;
            T[r] = *(const float4*)(xb + aT);
            B[r] = *(const float4*)(xb + aB);
        }
    };

    auto combine_sts = [&](int g, float* ns) {
        int px0r = wid*32 + g*4;
        float4 v[4];
        #pragma unroll
        for (int r = 0; r < 4; r++) {
            float4 wv = ((const float4*)(spar + (px0r + r)*8))[0];
            float wt_ = hi ? wv.y : wv.x;
            float wb_ = hi ? wv.w : wv.z;
            float sx = T[r].x*wt_ + B[r].x*wb_;
            float sy = T[r].y*wt_ + B[r].y*wb_;
            float sz = T[r].z*wt_ + B[r].z*wb_;
            float sw = T[r].w*wt_ + B[r].w*wb_;
            v[r].x = sx + __shfl_xor_sync(0xffffffffu, sx, 16);
            v[r].y = sy + __shfl_xor_sync(0xffffffffu, sy, 16);
            v[r].z = sz + __shfl_xor_sync(0xffffffffu, sz, 16);
            v[r].w = sw + __shfl_xor_sync(0xffffffffu, sw, 16);
        }
        int p4   = px0r >> 2;
        int slot = (p4 ^ (qh & 7)) * 4;
        if (hi == 0) {
            *(float4*)(ns + (4*qh + 0)*S_SS + slot) = make_float4(v[0].x, v[1].x, v[2].x, v[3].x);
            *(float4*)(ns + (4*qh + 1)*S_SS + slot) = make_float4(v[0].y, v[1].y, v[2].y, v[3].y);
        } else {
            *(float4*)(ns + (4*qh + 2)*S_SS + slot) = make_float4(v[0].z, v[1].z, v[2].z, v[3].z);
            *(float4*)(ns + (4*qh + 3)*S_SS + slot) = make_float4(v[0].w, v[1].w, v[2].w, v[3].w);
        }
    };

    // ---- prologue: tap 0 ----
    params(0); __syncwarp();
    stage_w(0, swtA);
    #pragma unroll 1
    for (int g = 0; g < 8; g++) { ldg_round(g); combine_sts(g, ssamA); }
    __syncthreads();

    // ---- main: GEMM(kt) overlapped with gather(kt+1) ----
    #pragma unroll 1
    for (int kt = 0; kt < 9; kt++) {
        float* cs = (kt & 1) ? ssamB : ssamA;
        float* cw = (kt & 1) ? swtB  : swtA;
        float* ns = (kt & 1) ? ssamA : ssamB;
        float* nw = (kt & 1) ? swtA  : swtB;
        bool more = (kt < 8);
        if (more) {
            params(kt + 1); __syncwarp();
            stage_w(kt + 1, nw);
        }
        #pragma unroll 1
        for (int g = 0; g < 8; g++) {
            if (more) ldg_round(g);
            // GEMM chunk: 8 c's
            #pragma unroll
            for (int cc = 0; cc < 8; cc++) {
                int c = g*8 + cc;
                const float* wrow = cw + c*S_WT + og*8;
                float4 wa = *(const float4*)(wrow);
                float4 wb2 = *(const float4*)(wrow + 4);
                int xr = (c >> 2) & 7;
                const float4* srow = (const float4*)(cs + c*S_SS);
                float4 sa = srow[(2*pg) ^ xr];
                float4 sb = srow[(2*pg + 1) ^ xr];
                ull s0 = ((ull*)&sa)[0], s1 = ((ull*)&sa)[1];
                ull s2 = ((ull*)&sb)[0], s3 = ((ull*)&sb)[1];
                float wf[8] = {wa.x, wa.y, wa.z, wa.w, wb2.x, wb2.y, wb2.z, wb2.w};
                #pragma unroll
                for (int o = 0; o < 8; o++) {
                    ull wd = dup2(wf[o]);
                    FMA2(acc[o][0], wd, s0);
                    FMA2(acc[o][1], wd, s1);
                    FMA2(acc[o][2], wd, s2);
                    FMA2(acc[o][3], wd, s3);
                }
            }
            if (more) combine_sts(g, ns);
        }
        __syncthreads();
    }

    // ---- epilogue ----
    float* ob = out + (size_t)b*64*HW + pix0 + pg*8;
    #pragma unroll
    for (int i = 0; i < 8; i++) {
        float* op = ob + (size_t)(og*8 + i)*HW;
        #pragma unroll
        for (int k = 0; k < 4; k++)
            *(ull*)(op + 2*k) = acc[i][k];
    }
}

// ---------------- launch ----------------
extern "C" void kernel_launch(void* const* d_in, const int* in_sizes, int n_in,
                              void* d_out, int out_size) {
    const float* x      = (const float*)d_in[0];
    const float* offset = (const float*)d_in[1];
    const float* weight = (const float*)d_in[2];
    const float* mw     = (const float*)d_in[3];
    const float* mb     = (const float*)d_in[4];
    float* out = (float*)d_out;
    (void)in_sizes; (void)n_in; (void)out_size;

    const int SMEM = (2*SS_FL + 2*WT_FL + 128*8) * 4;   // 106496 B
    cudaFuncSetAttribute(k_deform, cudaFuncAttributeMaxDynamicSharedMemorySize, SMEM);

    dim3 tg(HW/64, 4);
    k_nhwc<<<tg, 256>>>(x);
    k_mask<<<144, 256>>>(x, mw, mb, weight);
    dim3 grid(HW/128, 4);                // (72, 4)
    k_deform<<<grid, 128, SMEM>>>(offset, out);
}